// round 1
// baseline (speedup 1.0000x reference)
#include <cuda_runtime.h>

// HGAN triplet loss, restructured:
//   score[b] = b_fc + sum_k ( sum_{n,m} exp(S_k[n,m]) * F_k[n,m] ) / ( sum_{n,m} exp(S_k[n,m]) )
//   S_k[n,m] = sum_h W_att[k,h] * Aa[b,h,n] * Ac[b,h,m]      (b_att cancels in softmax)
//   F_k[n,m] = sum_h W_fc[k*H+h] * Aa[b,h,n] * Ac[b,h,m]     (final fc folded into aggregation)
//   loss = mean_b relu(score_neg - score_pos + 0.2)           (b_fc cancels in the difference)

#define B_ 32
#define N_ 256
#define E_ 300
#define H_ 256
#define K_ 8

// Scratch (device globals: allocation-free per harness rules)
__device__ float g_proj[3][B_][H_][N_];   // 0: anchor@W_a2h, 1: pos@W_c2h, 2: neg@W_c2h  (24 MB)
__device__ float g_num[2][B_][K_];
__device__ float g_den[2][B_][K_];

// ---------------------------------------------------------------------------
// Projection: g_proj[which][b][h][n] = bias[h] + sum_e X[b][n][e] * W[h][e]
// 64x64 output tile per block, E chunked by 20 (300 = 15*20).
// ---------------------------------------------------------------------------
__global__ __launch_bounds__(256)
void proj_kernel(const float* __restrict__ X, const float* __restrict__ W,
                 const float* __restrict__ bias, int which) {
    const int b  = blockIdx.z;
    const int h0 = blockIdx.y * 64;
    const int n0 = blockIdx.x * 64;
    const int tid = threadIdx.x;
    const int tx = tid & 15, ty = tid >> 4;

    __shared__ float Ws[20][68];   // [e][h], padded
    __shared__ float Xs[20][68];   // [e][n], padded

    float acc[4][4] = {};
    const float* Xb = X + (size_t)b * N_ * E_;

    for (int e0 = 0; e0 < E_; e0 += 20) {
        #pragma unroll
        for (int l = 0; l < 5; l++) {
            int idx = tid + l * 256;         // 0..1279 = 64 rows x 20 cols
            int rl = idx / 20;
            int el = idx - rl * 20;
            Ws[el][rl] = W [(h0 + rl) * E_ + e0 + el];
            Xs[el][rl] = Xb[(n0 + rl) * E_ + e0 + el];
        }
        __syncthreads();
        #pragma unroll
        for (int e = 0; e < 20; e++) {
            float4 wv4 = *(const float4*)&Ws[e][ty * 4];
            float4 xv4 = *(const float4*)&Xs[e][tx * 4];
            float wv[4] = {wv4.x, wv4.y, wv4.z, wv4.w};
            float xv[4] = {xv4.x, xv4.y, xv4.z, xv4.w};
            #pragma unroll
            for (int i = 0; i < 4; i++)
                #pragma unroll
                for (int j = 0; j < 4; j++)
                    acc[i][j] = fmaf(wv[i], xv[j], acc[i][j]);
        }
        __syncthreads();
    }

    #pragma unroll
    for (int i = 0; i < 4; i++) {
        int h = h0 + ty * 4 + i;
        float bb = bias[h];
        float4 o = make_float4(acc[i][0] + bb, acc[i][1] + bb,
                               acc[i][2] + bb, acc[i][3] + bb);
        *(float4*)&g_proj[which][b][h][n0 + tx * 4] = o;
    }
}

// ---------------------------------------------------------------------------
// Score: one block per (k, b, side). Dual GEMM (S and F share both operand
// tiles), streamed over 64x64 (n,m) tiles with H chunked by 16; softmax
// numerator/denominator accumulated in registers, block-reduced at the end.
// ---------------------------------------------------------------------------
__global__ __launch_bounds__(256, 3)
void score_kernel(const float* __restrict__ W_att, const float* __restrict__ W_fc) {
    const int k = blockIdx.x, b = blockIdx.y, side = blockIdx.z;
    const float* __restrict__ Aa = &g_proj[0][b][0][0];
    const float* __restrict__ Ac = &g_proj[1 + side][b][0][0];

    __shared__ float watt_s[H_], wfc_s[H_];
    __shared__ float A1s[16][64];   // watt[h]*Aa[h][n]
    __shared__ float A2s[16][64];   // wfc[h] *Aa[h][n]
    __shared__ float Cs [16][64];   // Ac[h][m]
    __shared__ float rn[8], rd[8];

    const int tid = threadIdx.x;
    const int tx = tid & 15, ty = tid >> 4;
    const int lc = tid & 63, lr = tid >> 6;

    for (int h = tid; h < H_; h += 256) {
        watt_s[h] = W_att[k * H_ + h];
        wfc_s[h]  = W_fc [k * H_ + h];
    }

    float num = 0.f, den = 0.f;

    for (int nt = 0; nt < 4; nt++) {
      for (int mt = 0; mt < 4; mt++) {
        const int n0 = nt * 64, m0 = mt * 64;
        float accS[4][4] = {}, accF[4][4] = {};

        for (int h0 = 0; h0 < H_; h0 += 16) {
            __syncthreads();   // also covers watt_s/wfc_s on the first pass
            #pragma unroll
            for (int i = 0; i < 4; i++) {
                int hh = h0 + lr + i * 4;
                float av = Aa[hh * N_ + n0 + lc];
                A1s[lr + i * 4][lc] = watt_s[hh] * av;
                A2s[lr + i * 4][lc] = wfc_s[hh]  * av;
                Cs [lr + i * 4][lc] = Ac[hh * N_ + m0 + lc];
            }
            __syncthreads();
            #pragma unroll
            for (int hh = 0; hh < 16; hh++) {
                float4 a14 = *(const float4*)&A1s[hh][ty * 4];
                float4 a24 = *(const float4*)&A2s[hh][ty * 4];
                float4 c4  = *(const float4*)&Cs [hh][tx * 4];
                float a1[4] = {a14.x, a14.y, a14.z, a14.w};
                float a2[4] = {a24.x, a24.y, a24.z, a24.w};
                float cv[4] = {c4.x,  c4.y,  c4.z,  c4.w};
                #pragma unroll
                for (int i = 0; i < 4; i++)
                    #pragma unroll
                    for (int j = 0; j < 4; j++) {
                        accS[i][j] = fmaf(a1[i], cv[j], accS[i][j]);
                        accF[i][j] = fmaf(a2[i], cv[j], accF[i][j]);
                    }
            }
        }

        // logits are O(0.2 std) -> exp without max-subtraction is safe
        #pragma unroll
        for (int i = 0; i < 4; i++)
            #pragma unroll
            for (int j = 0; j < 4; j++) {
                float e = __expf(accS[i][j]);
                den += e;
                num = fmaf(e, accF[i][j], num);
            }
      }
    }

    // block reduction
    #pragma unroll
    for (int o = 16; o; o >>= 1) {
        num += __shfl_down_sync(0xffffffffu, num, o);
        den += __shfl_down_sync(0xffffffffu, den, o);
    }
    const int wid = tid >> 5, lane = tid & 31;
    if (lane == 0) { rn[wid] = num; rd[wid] = den; }
    __syncthreads();
    if (tid == 0) {
        float sn = 0.f, sd = 0.f;
        #pragma unroll
        for (int w = 0; w < 8; w++) { sn += rn[w]; sd += rd[w]; }
        g_num[side][b][k] = sn;
        g_den[side][b][k] = sd;
    }
}

// ---------------------------------------------------------------------------
// Finalize: loss = mean_b relu(score_n - score_p + margin). b_fc cancels.
// ---------------------------------------------------------------------------
__global__ void finalize_kernel(float* __restrict__ out) {
    const int b = threadIdx.x;  // 32 threads
    float sp = 0.f, sn = 0.f;
    #pragma unroll
    for (int k = 0; k < K_; k++) {
        sp += g_num[0][b][k] / g_den[0][b][k];
        sn += g_num[1][b][k] / g_den[1][b][k];
    }
    float v = fmaxf(sn - sp + 0.2f, 0.f);
    #pragma unroll
    for (int o = 16; o; o >>= 1) v += __shfl_down_sync(0xffffffffu, v, o);
    if (b == 0) out[0] = v * (1.0f / B_);
}

// ---------------------------------------------------------------------------
extern "C" void kernel_launch(void* const* d_in, const int* in_sizes, int n_in,
                              void* d_out, int out_size) {
    const float* he_anchor = (const float*)d_in[0];
    const float* he_pos    = (const float*)d_in[1];
    const float* he_neg    = (const float*)d_in[2];
    const float* W_a2h     = (const float*)d_in[3];
    const float* b_a2h     = (const float*)d_in[4];
    const float* W_c2h     = (const float*)d_in[5];
    const float* b_c2h     = (const float*)d_in[6];
    const float* W_att     = (const float*)d_in[7];
    // d_in[8] = b_att  : cancels in per-(b,k) softmax -> unused
    const float* W_fc      = (const float*)d_in[9];
    // d_in[10] = b_fc  : cancels in score_n - score_p -> unused

    dim3 pgrid(4, 4, B_);
    proj_kernel<<<pgrid, 256>>>(he_anchor, W_a2h, b_a2h, 0);
    proj_kernel<<<pgrid, 256>>>(he_pos,    W_c2h, b_c2h, 1);
    proj_kernel<<<pgrid, 256>>>(he_neg,    W_c2h, b_c2h, 2);

    score_kernel<<<dim3(K_, B_, 2), 256>>>(W_att, W_fc);

    finalize_kernel<<<1, 32>>>((float*)d_out);
}